// round 2
// baseline (speedup 1.0000x reference)
#include <cuda_runtime.h>

// out[128,512] = x[128,1024] @ w[1024,512] + b   (exact algebraic reduction of
// the memristor reference: G_off and the pos/neg relu split cancel in the
// even-odd column subtraction, and K_V * k_g cancels with the final divide).

#define BATCH 128
#define NIN   1024
#define NOUT  512

#define BM 64
#define BN 64
#define BK 32
#define SPLITK 8
#define KCHUNK (NIN / SPLITK)   // 128

// ---------------------------------------------------------------------------
// Kernel 1: out[r, c] = b[c]  (bias init; split-K GEMM accumulates on top)
// 65536 floats = 16384 float4 -> 64 blocks x 256 threads
// ---------------------------------------------------------------------------
__global__ void init_bias_kernel(const float* __restrict__ bias,
                                 float* __restrict__ out) {
    int i = blockIdx.x * blockDim.x + threadIdx.x;      // 0..16383 (float4 idx)
    float4 bv = reinterpret_cast<const float4*>(bias)[i & (NOUT / 4 - 1)];
    reinterpret_cast<float4*>(out)[i] = bv;
}

// ---------------------------------------------------------------------------
// Kernel 2: split-K fp32 GEMM, 64x64 block tile, 4x4 register microtile,
// 256 threads (16x16 thread grid), atomicAdd epilogue.
// Grid: (NOUT/BN=8, BATCH/BM=2, SPLITK=8) = 128 blocks -> one wave on 148 SMs.
// ---------------------------------------------------------------------------
__global__ void __launch_bounds__(256, 1)
gemm_splitk_kernel(const float* __restrict__ x,
                   const float* __restrict__ w,
                   float* __restrict__ out) {
    __shared__ float xsT[BK][BM + 4];   // x tile, transposed (k-major rows)
    __shared__ float ws [BK][BN + 4];   // w tile, natural (k-major rows)

    const int tid  = threadIdx.x;
    const int tr   = tid >> 4;          // 0..15  -> output rows  tr*4..tr*4+3
    const int tc   = tid & 15;          // 0..15  -> output cols  tc*4..tc*4+3
    const int row0 = blockIdx.y * BM;
    const int col0 = blockIdx.x * BN;
    const int kbase = blockIdx.z * KCHUNK;

    // x-tile loader mapping: 64 rows x 8 float4 along k = 512 float4, 2/thread
    const int lxr = tid >> 2;           // row within tile: 0..63
    const int lxj = tid & 3;            // float4 slot j and j+4 (8 per row)
    // w-tile loader mapping: 32 k-rows x 16 float4 = 512 float4, 2/thread
    const int lwk = tid >> 3;           // k-row: 0..31
    const int lwj = tid & 7;            // float4 slot j and j+8

    float acc[4][4] = {};

    #pragma unroll
    for (int s = 0; s < KCHUNK / BK; ++s) {
        const int ks = kbase + s * BK;

        // ---- stage x tile (transposed store) ----
        {
            const float* xr = &x[(row0 + lxr) * NIN + ks];
            float4 v0 = *reinterpret_cast<const float4*>(&xr[lxj * 4]);
            float4 v1 = *reinterpret_cast<const float4*>(&xr[(lxj + 4) * 4]);
            int k0 = lxj * 4;
            xsT[k0 + 0][lxr] = v0.x;  xsT[k0 + 1][lxr] = v0.y;
            xsT[k0 + 2][lxr] = v0.z;  xsT[k0 + 3][lxr] = v0.w;
            int k1 = (lxj + 4) * 4;
            xsT[k1 + 0][lxr] = v1.x;  xsT[k1 + 1][lxr] = v1.y;
            xsT[k1 + 2][lxr] = v1.z;  xsT[k1 + 3][lxr] = v1.w;
        }
        // ---- stage w tile ----
        {
            const float* wr = &w[(ks + lwk) * NOUT + col0];
            float4 v0 = *reinterpret_cast<const float4*>(&wr[lwj * 4]);
            float4 v1 = *reinterpret_cast<const float4*>(&wr[(lwj + 8) * 4]);
            *reinterpret_cast<float4*>(&ws[lwk][lwj * 4])       = v0;
            *reinterpret_cast<float4*>(&ws[lwk][(lwj + 8) * 4]) = v1;
        }
        __syncthreads();

        // ---- 4x4 microtile FMAs over BK ----
        #pragma unroll
        for (int k = 0; k < BK; ++k) {
            float4 a = *reinterpret_cast<const float4*>(&xsT[k][tr * 4]);
            float4 bv = *reinterpret_cast<const float4*>(&ws[k][tc * 4]);
            acc[0][0] += a.x * bv.x;  acc[0][1] += a.x * bv.y;
            acc[0][2] += a.x * bv.z;  acc[0][3] += a.x * bv.w;
            acc[1][0] += a.y * bv.x;  acc[1][1] += a.y * bv.y;
            acc[1][2] += a.y * bv.z;  acc[1][3] += a.y * bv.w;
            acc[2][0] += a.z * bv.x;  acc[2][1] += a.z * bv.y;
            acc[2][2] += a.z * bv.z;  acc[2][3] += a.z * bv.w;
            acc[3][0] += a.w * bv.x;  acc[3][1] += a.w * bv.y;
            acc[3][2] += a.w * bv.z;  acc[3][3] += a.w * bv.w;
        }
        __syncthreads();
    }

    // ---- split-K accumulate into out (pre-initialized with bias) ----
    #pragma unroll
    for (int i = 0; i < 4; ++i) {
        float* orow = &out[(row0 + tr * 4 + i) * NOUT + col0 + tc * 4];
        #pragma unroll
        for (int j = 0; j < 4; ++j) {
            atomicAdd(&orow[j], acc[i][j]);
        }
    }
}

// ---------------------------------------------------------------------------
extern "C" void kernel_launch(void* const* d_in, const int* in_sizes, int n_in,
                              void* d_out, int out_size) {
    const float* x = (const float*)d_in[0];   // (128, 1024)
    const float* w = (const float*)d_in[1];   // (1024, 512)
    const float* b = (const float*)d_in[2];   // (512,)
    float* out = (float*)d_out;               // (128, 512)

    init_bias_kernel<<<64, 256>>>(b, out);
    gemm_splitk_kernel<<<dim3(NOUT / BN, BATCH / BM, SPLITK), 256>>>(x, w, out);
}